// round 14
// baseline (speedup 1.0000x reference)
#include <cuda_runtime.h>
#include <cstdint>

// Problem constants
#define DD   256
#define NQ   4
#define KK   1024
#define NTOT 131072

// Tiling
#define BM   64               // rows per CTA (8 warps x 8 rows), resident in smem
#define BNC  256              // codes per chunk
#define BK   16               // d per staged B chunk
#define NTHREADS 256
#define NITER_T  256          // 4 stages * 4 cc * 16 dk

// Scratch (read-only after prep)
__device__ float g_cbT[(size_t)NQ * DD * KK];   // codebooks transposed [s][d][k]
__device__ float g_c2[NQ * KK];                 // ||c||^2 per code

// ---------------- packed f32x2 helpers ----------------
__device__ __forceinline__ unsigned long long pack2(float x) {
    unsigned long long r;
    unsigned int xi = __float_as_uint(x);
    asm("mov.b64 %0, {%1, %1};" : "=l"(r) : "r"(xi));
    return r;
}
__device__ __forceinline__ void ffma2(unsigned long long &acc,
                                      unsigned long long a,
                                      unsigned long long b) {
    asm("fma.rn.f32x2 %0, %1, %2, %0;" : "+l"(acc) : "l"(a), "l"(b));
}
__device__ __forceinline__ float2 unpack2(unsigned long long v) {
    unsigned int lo, hi;
    asm("mov.b64 {%0, %1}, %2;" : "=r"(lo), "=r"(hi) : "l"(v));
    return make_float2(__uint_as_float(lo), __uint_as_float(hi));
}
__device__ __forceinline__ void cpasync16(uint32_t s, const void* g) {
    asm volatile("cp.async.cg.shared.global [%0], [%1], 16;" :: "r"(s), "l"(g));
}

// ---------------- codebook transpose [NQ][K][D] -> [NQ][D][K] ----------------
__global__ void transpose_k(const float* __restrict__ src, float* __restrict__ dst,
                            int R, int C, long srcBatch, long dstBatch) {
    __shared__ float tile[32][33];
    const float* s = src + (long)blockIdx.z * srcBatch;
    float*       d = dst + (long)blockIdx.z * dstBatch;
    int c0 = blockIdx.x * 32, r0 = blockIdx.y * 32;
    int tx = threadIdx.x, ty = threadIdx.y;           // 32 x 8
    #pragma unroll
    for (int i = 0; i < 32; i += 8)
        tile[ty + i][tx] = s[(long)(r0 + ty + i) * C + c0 + tx];
    __syncthreads();
    #pragma unroll
    for (int i = 0; i < 32; i += 8)
        d[(long)(c0 + ty + i) * R + r0 + tx] = tile[tx][ty + i];
}

// ---------------- ||c||^2 per code ----------------
__global__ void c2_k(const float* __restrict__ cb) {
    int w = (blockIdx.x * blockDim.x + threadIdx.x) >> 5;
    int lane = threadIdx.x & 31;
    if (w >= NQ * KK) return;
    const float* row = cb + (long)w * DD;
    float s = 0.f;
    #pragma unroll
    for (int j = lane; j < DD; j += 32) { float v = row[j]; s = fmaf(v, v, s); }
    #pragma unroll
    for (int o = 16; o; o >>= 1) s += __shfl_xor_sync(0xffffffffu, s, o);
    if (lane == 0) g_c2[w] = s;
}

// ---------------- fused all-stages kernel ----------------
// Residual tile [256 d][64 rows] lives in smem for the whole kernel.
// 8 warps; warp w owns rows w*8..w*8+7, all 256 codes of each chunk.
// Lane l owns codes {cc*256 + l*4 + q} and {cc*256 + 128 + l*4 + q}, q=0..3.
__global__ void __launch_bounds__(NTHREADS, 2)
rvq_fused_k(const float* __restrict__ x, const float* __restrict__ cb,
            float* __restrict__ outQ, int writeQ,
            float* __restrict__ outCodes, int writeCodes) {
    extern __shared__ float sm[];
    float* Rs = sm;                           // [256][64]  64KB resident residual
    float* Bs = Rs + DD * BM;                 // [2][16][256]  2x16KB B chunks
    int*   codes_all = (int*)(Bs + 2 * BK * BNC);   // [4][64]

    const int t = threadIdx.x, lane = t & 31, w = t >> 5;
    const long rowBase = (long)blockIdx.x * BM;

    const uint32_t BsA = (uint32_t)__cvta_generic_to_shared(Bs);

    // stage B chunk for linear iteration JN into buffer JN&1
    #define STAGE_B(JN) do {                                                       \
        const int _s = (JN) >> 6, _cc = ((JN) >> 4) & 3, _dk = (JN) & 15;          \
        const uint32_t _bb = BsA + (uint32_t)((JN) & 1) * (BK * BNC * 4);          \
        const float* _src = g_cbT + ((size_t)_s * DD + _dk * BK) * KK + _cc * BNC; \
        _Pragma("unroll")                                                          \
        for (int k = 0; k < 4; k++) {                                              \
            int i4 = t + k * NTHREADS;            /* [0,1024): 16dd x 64 u16B */   \
            int dd = i4 >> 6, c4 = i4 & 63;                                        \
            cpasync16(_bb + (uint32_t)(dd * BNC + c4 * 4) * 4,                     \
                      &_src[(size_t)dd * KK + c4 * 4]);                            \
        }                                                                          \
        asm volatile("cp.async.commit_group;" ::: "memory");                       \
    } while (0)

    STAGE_B(0);

    // residual tile: direct from row-major x with in-kernel transpose.
    // thread: row = t&63, d-group = t>>6 (64 dims). LDG.128 sectored per thread;
    // STS conflict-free (lanes -> distinct rows -> distinct banks).
    {
        const int r = t & 63, dg = t >> 6;
        const float* xrow = x + (rowBase + r) * DD + dg * 64;
        #pragma unroll
        for (int i = 0; i < 16; i++) {
            float4 v = *(const float4*)&xrow[i * 4];
            Rs[(dg * 64 + i * 4 + 0) * BM + r] = v.x;
            Rs[(dg * 64 + i * 4 + 1) * BM + r] = v.y;
            Rs[(dg * 64 + i * 4 + 2) * BM + r] = v.z;
            Rs[(dg * 64 + i * 4 + 3) * BM + r] = v.w;
        }
    }

    float bestd[8];
    int   bestc[8];
    #pragma unroll
    for (int r = 0; r < 8; r++) { bestd[r] = 3.4e38f; bestc[r] = 0; }

    unsigned long long acc[8][4];   // [row][code-pair]: cp0/1 = lane*4+{01,23}, cp2/3 = +128

    for (int J = 0; J < NITER_T; J++) {
        asm volatile("cp.async.wait_group 0;" ::: "memory");
        __syncthreads();
        // safe prefetch point: all warps completed compute(J-1), the last reader
        // of buffer (J+1)&1.
        if (J + 1 < NITER_T) STAGE_B(J + 1);

        const int s = J >> 6, cc = (J >> 4) & 3, dk = J & 15;
        const float* bbuf = Bs + (J & 1) * (BK * BNC);

        if (dk == 0) {
            #pragma unroll
            for (int r = 0; r < 8; r++)
                #pragma unroll
                for (int cp = 0; cp < 4; cp++) acc[r][cp] = 0ull;
        }

        // unroll 8 (2 iterations): halves the body to ~L0 I-cache size while
        // keeping identical data path and accumulation order.
        #pragma unroll 8
        for (int dd = 0; dd < BK; dd++) {
            const float4 a0 = *(const float4*)&Rs[(dk * BK + dd) * BM + w * 8];       // broadcast
            const float4 a1 = *(const float4*)&Rs[(dk * BK + dd) * BM + w * 8 + 4];   // broadcast
            const ulonglong2 b0 = *(const ulonglong2*)&bbuf[dd * BNC + lane * 4];        // dense
            const ulonglong2 b1 = *(const ulonglong2*)&bbuf[dd * BNC + 128 + lane * 4];  // dense
            unsigned long long A[8];
            A[0] = pack2(a0.x); A[1] = pack2(a0.y); A[2] = pack2(a0.z); A[3] = pack2(a0.w);
            A[4] = pack2(a1.x); A[5] = pack2(a1.y); A[6] = pack2(a1.z); A[7] = pack2(a1.w);
            #pragma unroll
            for (int r = 0; r < 8; r++) {
                ffma2(acc[r][0], A[r], b0.x);
                ffma2(acc[r][1], A[r], b0.y);
                ffma2(acc[r][2], A[r], b1.x);
                ffma2(acc[r][3], A[r], b1.y);
            }
        }

        if (dk == 15) {
            // dist = c2 - 2*dot ; codes ascend within each thread -> lexicographic argmin
            const float* c2p = g_c2 + s * KK;
            const float4 c2a = *(const float4*)&c2p[cc * BNC + lane * 4];
            const float4 c2b = *(const float4*)&c2p[cc * BNC + 128 + lane * 4];
            #pragma unroll
            for (int r = 0; r < 8; r++) {
                #pragma unroll
                for (int cp = 0; cp < 4; cp++) {
                    float2 dv = unpack2(acc[r][cp]);
                    int cg0 = cc * BNC + ((cp & 2) ? 128 : 0) + lane * 4 + 2 * (cp & 1);
                    float cva = (cp == 0) ? c2a.x : (cp == 1) ? c2a.z : (cp == 2) ? c2b.x : c2b.z;
                    float cvb = (cp == 0) ? c2a.y : (cp == 1) ? c2a.w : (cp == 2) ? c2b.y : c2b.w;
                    float d0 = fmaf(-2.f, dv.x, cva);
                    float d1 = fmaf(-2.f, dv.y, cvb);
                    if (d0 < bestd[r] || (d0 == bestd[r] && cg0 < bestc[r])) { bestd[r] = d0; bestc[r] = cg0; }
                    if (d1 < bestd[r] || (d1 == bestd[r] && cg0 + 1 < bestc[r])) { bestd[r] = d1; bestc[r] = cg0 + 1; }
                }
            }
        }

        // stage-end: argmin merge + in-smem residual update
        if ((J & 63) == 63) {
            #pragma unroll
            for (int r = 0; r < 8; r++) {
                float d = bestd[r]; int c = bestc[r];
                #pragma unroll
                for (int o = 16; o; o >>= 1) {
                    float od = __shfl_xor_sync(0xffffffffu, d, o);
                    int   oc = __shfl_xor_sync(0xffffffffu, c, o);
                    if (od < d || (od == d && oc < c)) { d = od; c = oc; }
                }
                if (lane == 0) codes_all[s * BM + w * 8 + r] = c;
                bestd[r] = 3.4e38f; bestc[r] = 0;
            }
            __syncthreads();            // codes_all visible to all
            if (s < NQ - 1) {
                // Rs[d][r] -= cb_s[code_r][d]; thread: r = t&63, d-group = t>>6.
                // float4 gather (16 LDG.128) + conflict-free scalar smem RMW.
                const int r = t & 63, dg = t >> 6;
                const int code = codes_all[s * BM + r];
                const float* crow = cb + ((size_t)s * KK + code) * DD + dg * 64;
                #pragma unroll
                for (int i = 0; i < 16; i++) {
                    float4 v = *(const float4*)&crow[i * 4];
                    Rs[(dg * 64 + i * 4 + 0) * BM + r] -= v.x;
                    Rs[(dg * 64 + i * 4 + 1) * BM + r] -= v.y;
                    Rs[(dg * 64 + i * 4 + 2) * BM + r] -= v.z;
                    Rs[(dg * 64 + i * 4 + 3) * BM + r] -= v.w;
                }
            }
            // the next loop-head __syncthreads orders this update before stage s+1 compute
        }
    }
    #undef STAGE_B

    // codes output: one coalesced STG.128 per row (all 4 stages packed)
    if (writeCodes && t < BM) {
        float4 cv;
        cv.x = (float)codes_all[t];
        cv.y = (float)codes_all[BM + t];
        cv.z = (float)codes_all[2 * BM + t];
        cv.w = (float)codes_all[3 * BM + t];
        *(float4*)&outCodes[(rowBase + t) * NQ] = cv;
    }

    // quantised output: out[row] = ((cb0[c0] + cb1[c1]) + cb2[c2]) + cb3[c3]
    // (matches the reference scan's sequential total accumulation order)
    if (writeQ) {
        #pragma unroll
        for (int rr = 0; rr < 8; rr++) {
            int row = w * 8 + rr;
            int c0 = codes_all[row];
            int c1 = codes_all[BM + row];
            int c2 = codes_all[2 * BM + row];
            int c3 = codes_all[3 * BM + row];
            const float4* q0 = (const float4*)(cb + (size_t)c0 * DD);
            const float4* q1 = (const float4*)(cb + ((size_t)KK + c1) * DD);
            const float4* q2 = (const float4*)(cb + ((size_t)2 * KK + c2) * DD);
            const float4* q3 = (const float4*)(cb + ((size_t)3 * KK + c3) * DD);
            float4* orow = (float4*)(outQ + (rowBase + row) * DD);
            #pragma unroll
            for (int dq = 0; dq < 2; dq++) {
                int idx = lane + dq * 32;
                float4 v0 = q0[idx], v1 = q1[idx], v2 = q2[idx], v3 = q3[idx];
                float4 o;
                o.x = ((v0.x + v1.x) + v2.x) + v3.x;
                o.y = ((v0.y + v1.y) + v2.y) + v3.y;
                o.z = ((v0.z + v1.z) + v2.z) + v3.z;
                o.w = ((v0.w + v1.w) + v2.w) + v3.w;
                orow[idx] = o;
            }
        }
    }
}

// ---------------- launch ----------------
extern "C" void kernel_launch(void* const* d_in, const int* in_sizes, int n_in,
                              void* d_out, int out_size) {
    const float* x  = (const float*)d_in[0];
    const float* cb = (const float*)d_in[1];
    float* out = (float*)d_out;

    const long QE = (long)NTOT * DD;
    const long CE = (long)NTOT * NQ;

    int writeQ = (out_size >= QE) ? 1 : 0;
    float* outCodes = nullptr;
    int writeCodes = 0;
    if ((long)out_size >= QE + CE) { outCodes = out + QE; writeCodes = 1; }
    else if (!writeQ && (long)out_size >= CE) { outCodes = out; writeCodes = 1; }

    const int SMEM = (DD * BM + 2 * BK * BNC) * 4 + NQ * BM * 4;   // 99328 B
    cudaFuncSetAttribute(rvq_fused_k, cudaFuncAttributeMaxDynamicSharedMemorySize, SMEM);

    float* cbT_ptr = nullptr;
    cudaGetSymbolAddress((void**)&cbT_ptr, g_cbT);

    dim3 tb(32, 8);
    // codebooks [NQ][K][D] -> [NQ][D][K]
    transpose_k<<<dim3(DD / 32, KK / 32, NQ), tb>>>(cb, cbT_ptr, KK, DD,
                                                    (long)KK * DD, (long)DD * KK);
    c2_k<<<(NQ * KK * 32 + 255) / 256, 256>>>(cb);

    rvq_fused_k<<<NTOT / BM, NTHREADS, SMEM>>>(x, cb, out, writeQ, outCodes, writeCodes);
}

// round 15
// speedup vs baseline: 1.0645x; 1.0645x over previous
#include <cuda_runtime.h>
#include <cstdint>

// Problem constants
#define DD   256
#define NQ   4
#define KK   1024
#define NTOT 131072

// Tiling
#define BM   64               // rows per CTA (8 warps x 8 rows), resident in smem
#define BNC  256              // codes per chunk
#define BK   16               // d per staged B chunk
#define NTHREADS 256
#define NITER_T  256          // 4 stages * 4 cc * 16 dk

// Scratch (read-only after prep)
__device__ float g_cbT[(size_t)NQ * DD * KK];   // codebooks transposed [s][d][k]
__device__ float g_c2[NQ * KK];                 // ||c||^2 per code

// ---------------- packed f32x2 helpers ----------------
__device__ __forceinline__ unsigned long long pack2(float x) {
    unsigned long long r;
    unsigned int xi = __float_as_uint(x);
    asm("mov.b64 %0, {%1, %1};" : "=l"(r) : "r"(xi));
    return r;
}
__device__ __forceinline__ void ffma2(unsigned long long &acc,
                                      unsigned long long a,
                                      unsigned long long b) {
    asm("fma.rn.f32x2 %0, %1, %2, %0;" : "+l"(acc) : "l"(a), "l"(b));
}
__device__ __forceinline__ float2 unpack2(unsigned long long v) {
    unsigned int lo, hi;
    asm("mov.b64 {%0, %1}, %2;" : "=r"(lo), "=r"(hi) : "l"(v));
    return make_float2(__uint_as_float(lo), __uint_as_float(hi));
}
__device__ __forceinline__ void cpasync16(uint32_t s, const void* g) {
    asm volatile("cp.async.cg.shared.global [%0], [%1], 16;" :: "r"(s), "l"(g));
}

// ---------------- codebook transpose [NQ][K][D] -> [NQ][D][K] ----------------
__global__ void transpose_k(const float* __restrict__ src, float* __restrict__ dst,
                            int R, int C, long srcBatch, long dstBatch) {
    __shared__ float tile[32][33];
    const float* s = src + (long)blockIdx.z * srcBatch;
    float*       d = dst + (long)blockIdx.z * dstBatch;
    int c0 = blockIdx.x * 32, r0 = blockIdx.y * 32;
    int tx = threadIdx.x, ty = threadIdx.y;           // 32 x 8
    #pragma unroll
    for (int i = 0; i < 32; i += 8)
        tile[ty + i][tx] = s[(long)(r0 + ty + i) * C + c0 + tx];
    __syncthreads();
    #pragma unroll
    for (int i = 0; i < 32; i += 8)
        d[(long)(c0 + ty + i) * R + r0 + tx] = tile[tx][ty + i];
}

// ---------------- ||c||^2 per code ----------------
__global__ void c2_k(const float* __restrict__ cb) {
    int w = (blockIdx.x * blockDim.x + threadIdx.x) >> 5;
    int lane = threadIdx.x & 31;
    if (w >= NQ * KK) return;
    const float* row = cb + (long)w * DD;
    float s = 0.f;
    #pragma unroll
    for (int j = lane; j < DD; j += 32) { float v = row[j]; s = fmaf(v, v, s); }
    #pragma unroll
    for (int o = 16; o; o >>= 1) s += __shfl_xor_sync(0xffffffffu, s, o);
    if (lane == 0) g_c2[w] = s;
}

// ---------------- fused all-stages kernel (converged configuration) ----------------
// Residual tile [256 d][64 rows] lives in smem for the whole kernel.
// 8 warps; warp w owns rows w*8..w*8+7, all 256 codes of each chunk.
// Lane l owns codes {cc*256 + l*4 + q} and {cc*256 + 128 + l*4 + q}, q=0..3.
__global__ void __launch_bounds__(NTHREADS, 2)
rvq_fused_k(const float* __restrict__ x, const float* __restrict__ cb,
            float* __restrict__ outQ, int writeQ,
            float* __restrict__ outCodes, int writeCodes) {
    extern __shared__ float sm[];
    float* Rs = sm;                           // [256][64]  64KB resident residual
    float* Bs = Rs + DD * BM;                 // [2][16][256]  2x16KB B chunks
    int*   codes_all = (int*)(Bs + 2 * BK * BNC);   // [4][64]

    const int t = threadIdx.x, lane = t & 31, w = t >> 5;
    const long rowBase = (long)blockIdx.x * BM;

    const uint32_t BsA = (uint32_t)__cvta_generic_to_shared(Bs);

    // stage B chunk for linear iteration JN into buffer JN&1
    #define STAGE_B(JN) do {                                                       \
        const int _s = (JN) >> 6, _cc = ((JN) >> 4) & 3, _dk = (JN) & 15;          \
        const uint32_t _bb = BsA + (uint32_t)((JN) & 1) * (BK * BNC * 4);          \
        const float* _src = g_cbT + ((size_t)_s * DD + _dk * BK) * KK + _cc * BNC; \
        _Pragma("unroll")                                                          \
        for (int k = 0; k < 4; k++) {                                              \
            int i4 = t + k * NTHREADS;            /* [0,1024): 16dd x 64 u16B */   \
            int dd = i4 >> 6, c4 = i4 & 63;                                        \
            cpasync16(_bb + (uint32_t)(dd * BNC + c4 * 4) * 4,                     \
                      &_src[(size_t)dd * KK + c4 * 4]);                            \
        }                                                                          \
        asm volatile("cp.async.commit_group;" ::: "memory");                       \
    } while (0)

    STAGE_B(0);

    // residual tile: direct from row-major x with in-kernel transpose.
    // thread: row = t&63, d-group = t>>6 (64 dims). LDG.128 sectored per thread;
    // STS conflict-free (lanes -> distinct rows -> distinct banks).
    {
        const int r = t & 63, dg = t >> 6;
        const float* xrow = x + (rowBase + r) * DD + dg * 64;
        #pragma unroll
        for (int i = 0; i < 16; i++) {
            float4 v = *(const float4*)&xrow[i * 4];
            Rs[(dg * 64 + i * 4 + 0) * BM + r] = v.x;
            Rs[(dg * 64 + i * 4 + 1) * BM + r] = v.y;
            Rs[(dg * 64 + i * 4 + 2) * BM + r] = v.z;
            Rs[(dg * 64 + i * 4 + 3) * BM + r] = v.w;
        }
    }

    float bestd[8];
    int   bestc[8];
    #pragma unroll
    for (int r = 0; r < 8; r++) { bestd[r] = 3.4e38f; bestc[r] = 0; }

    unsigned long long acc[8][4];   // [row][code-pair]: cp0/1 = lane*4+{01,23}, cp2/3 = +128

    for (int J = 0; J < NITER_T; J++) {
        asm volatile("cp.async.wait_group 0;" ::: "memory");
        __syncthreads();
        // safe prefetch point: all warps completed compute(J-1), the last reader
        // of buffer (J+1)&1.
        if (J + 1 < NITER_T) STAGE_B(J + 1);

        const int s = J >> 6, cc = (J >> 4) & 3, dk = J & 15;
        const float* bbuf = Bs + (J & 1) * (BK * BNC);

        if (dk == 0) {
            #pragma unroll
            for (int r = 0; r < 8; r++)
                #pragma unroll
                for (int cp = 0; cp < 4; cp++) acc[r][cp] = 0ull;
        }

        #pragma unroll
        for (int dd = 0; dd < BK; dd++) {
            const float4 a0 = *(const float4*)&Rs[(dk * BK + dd) * BM + w * 8];       // broadcast
            const float4 a1 = *(const float4*)&Rs[(dk * BK + dd) * BM + w * 8 + 4];   // broadcast
            const ulonglong2 b0 = *(const ulonglong2*)&bbuf[dd * BNC + lane * 4];        // dense
            const ulonglong2 b1 = *(const ulonglong2*)&bbuf[dd * BNC + 128 + lane * 4];  // dense
            unsigned long long A[8];
            A[0] = pack2(a0.x); A[1] = pack2(a0.y); A[2] = pack2(a0.z); A[3] = pack2(a0.w);
            A[4] = pack2(a1.x); A[5] = pack2(a1.y); A[6] = pack2(a1.z); A[7] = pack2(a1.w);
            #pragma unroll
            for (int r = 0; r < 8; r++) {
                ffma2(acc[r][0], A[r], b0.x);
                ffma2(acc[r][1], A[r], b0.y);
                ffma2(acc[r][2], A[r], b1.x);
                ffma2(acc[r][3], A[r], b1.y);
            }
        }

        if (dk == 15) {
            // dist = c2 - 2*dot ; codes ascend within each thread -> lexicographic argmin
            const float* c2p = g_c2 + s * KK;
            const float4 c2a = *(const float4*)&c2p[cc * BNC + lane * 4];
            const float4 c2b = *(const float4*)&c2p[cc * BNC + 128 + lane * 4];
            #pragma unroll
            for (int r = 0; r < 8; r++) {
                #pragma unroll
                for (int cp = 0; cp < 4; cp++) {
                    float2 dv = unpack2(acc[r][cp]);
                    int cg0 = cc * BNC + ((cp & 2) ? 128 : 0) + lane * 4 + 2 * (cp & 1);
                    float cva = (cp == 0) ? c2a.x : (cp == 1) ? c2a.z : (cp == 2) ? c2b.x : c2b.z;
                    float cvb = (cp == 0) ? c2a.y : (cp == 1) ? c2a.w : (cp == 2) ? c2b.y : c2b.w;
                    float d0 = fmaf(-2.f, dv.x, cva);
                    float d1 = fmaf(-2.f, dv.y, cvb);
                    if (d0 < bestd[r] || (d0 == bestd[r] && cg0 < bestc[r])) { bestd[r] = d0; bestc[r] = cg0; }
                    if (d1 < bestd[r] || (d1 == bestd[r] && cg0 + 1 < bestc[r])) { bestd[r] = d1; bestc[r] = cg0 + 1; }
                }
            }
        }

        // stage-end: argmin merge + in-smem residual update
        if ((J & 63) == 63) {
            #pragma unroll
            for (int r = 0; r < 8; r++) {
                float d = bestd[r]; int c = bestc[r];
                #pragma unroll
                for (int o = 16; o; o >>= 1) {
                    float od = __shfl_xor_sync(0xffffffffu, d, o);
                    int   oc = __shfl_xor_sync(0xffffffffu, c, o);
                    if (od < d || (od == d && oc < c)) { d = od; c = oc; }
                }
                if (lane == 0) codes_all[s * BM + w * 8 + r] = c;
                bestd[r] = 3.4e38f; bestc[r] = 0;
            }
            __syncthreads();            // codes_all visible to all
            if (s < NQ - 1) {
                // Rs[d][r] -= cb_s[code_r][d]; thread: r = t&63, d-group = t>>6.
                // float4 gather (16 LDG.128) + conflict-free scalar smem RMW.
                const int r = t & 63, dg = t >> 6;
                const int code = codes_all[s * BM + r];
                const float* crow = cb + ((size_t)s * KK + code) * DD + dg * 64;
                #pragma unroll
                for (int i = 0; i < 16; i++) {
                    float4 v = *(const float4*)&crow[i * 4];
                    Rs[(dg * 64 + i * 4 + 0) * BM + r] -= v.x;
                    Rs[(dg * 64 + i * 4 + 1) * BM + r] -= v.y;
                    Rs[(dg * 64 + i * 4 + 2) * BM + r] -= v.z;
                    Rs[(dg * 64 + i * 4 + 3) * BM + r] -= v.w;
                }
            }
            // the next loop-head __syncthreads orders this update before stage s+1 compute
        }
    }
    #undef STAGE_B

    // codes output: one coalesced STG.128 per row (all 4 stages packed)
    if (writeCodes && t < BM) {
        float4 cv;
        cv.x = (float)codes_all[t];
        cv.y = (float)codes_all[BM + t];
        cv.z = (float)codes_all[2 * BM + t];
        cv.w = (float)codes_all[3 * BM + t];
        *(float4*)&outCodes[(rowBase + t) * NQ] = cv;
    }

    // quantised output: out[row] = ((cb0[c0] + cb1[c1]) + cb2[c2]) + cb3[c3]
    // (matches the reference scan's sequential total accumulation order)
    if (writeQ) {
        #pragma unroll
        for (int rr = 0; rr < 8; rr++) {
            int row = w * 8 + rr;
            int c0 = codes_all[row];
            int c1 = codes_all[BM + row];
            int c2 = codes_all[2 * BM + row];
            int c3 = codes_all[3 * BM + row];
            const float4* q0 = (const float4*)(cb + (size_t)c0 * DD);
            const float4* q1 = (const float4*)(cb + ((size_t)KK + c1) * DD);
            const float4* q2 = (const float4*)(cb + ((size_t)2 * KK + c2) * DD);
            const float4* q3 = (const float4*)(cb + ((size_t)3 * KK + c3) * DD);
            float4* orow = (float4*)(outQ + (rowBase + row) * DD);
            #pragma unroll
            for (int dq = 0; dq < 2; dq++) {
                int idx = lane + dq * 32;
                float4 v0 = q0[idx], v1 = q1[idx], v2 = q2[idx], v3 = q3[idx];
                float4 o;
                o.x = ((v0.x + v1.x) + v2.x) + v3.x;
                o.y = ((v0.y + v1.y) + v2.y) + v3.y;
                o.z = ((v0.z + v1.z) + v2.z) + v3.z;
                o.w = ((v0.w + v1.w) + v2.w) + v3.w;
                orow[idx] = o;
            }
        }
    }
}

// ---------------- launch ----------------
extern "C" void kernel_launch(void* const* d_in, const int* in_sizes, int n_in,
                              void* d_out, int out_size) {
    const float* x  = (const float*)d_in[0];
    const float* cb = (const float*)d_in[1];
    float* out = (float*)d_out;

    const long QE = (long)NTOT * DD;
    const long CE = (long)NTOT * NQ;

    int writeQ = (out_size >= QE) ? 1 : 0;
    float* outCodes = nullptr;
    int writeCodes = 0;
    if ((long)out_size >= QE + CE) { outCodes = out + QE; writeCodes = 1; }
    else if (!writeQ && (long)out_size >= CE) { outCodes = out; writeCodes = 1; }

    const int SMEM = (DD * BM + 2 * BK * BNC) * 4 + NQ * BM * 4;   // 99328 B
    cudaFuncSetAttribute(rvq_fused_k, cudaFuncAttributeMaxDynamicSharedMemorySize, SMEM);

    float* cbT_ptr = nullptr;
    cudaGetSymbolAddress((void**)&cbT_ptr, g_cbT);

    dim3 tb(32, 8);
    // codebooks [NQ][K][D] -> [NQ][D][K]
    transpose_k<<<dim3(DD / 32, KK / 32, NQ), tb>>>(cb, cbT_ptr, KK, DD,
                                                    (long)KK * DD, (long)DD * KK);
    c2_k<<<(NQ * KK * 32 + 255) / 256, 256>>>(cb);

    rvq_fused_k<<<NTOT / BM, NTHREADS, SMEM>>>(x, cb, out, writeQ, outCodes, writeCodes);
}

// round 16
// speedup vs baseline: 1.0647x; 1.0002x over previous
#include <cuda_runtime.h>
#include <cstdint>

// Problem constants
#define DD   256
#define NQ   4
#define KK   1024
#define NTOT 131072

// Tiling
#define BM   64               // rows per CTA (8 warps x 8 rows), resident in smem
#define BNC  256              // codes per chunk
#define BK   16               // d per staged B chunk
#define NTHREADS 256
#define NITER_T  256          // 4 stages * 4 cc * 16 dk

// Scratch (read-only after prep)
__device__ float g_cbT[(size_t)NQ * DD * KK];   // codebooks transposed [s][d][k]
__device__ float g_c2[NQ * KK];                 // ||c||^2 per code

// ---------------- packed f32x2 helpers ----------------
__device__ __forceinline__ unsigned long long pack2(float x) {
    unsigned long long r;
    unsigned int xi = __float_as_uint(x);
    asm("mov.b64 %0, {%1, %1};" : "=l"(r) : "r"(xi));
    return r;
}
__device__ __forceinline__ void ffma2(unsigned long long &acc,
                                      unsigned long long a,
                                      unsigned long long b) {
    asm("fma.rn.f32x2 %0, %1, %2, %0;" : "+l"(acc) : "l"(a), "l"(b));
}
__device__ __forceinline__ float2 unpack2(unsigned long long v) {
    unsigned int lo, hi;
    asm("mov.b64 {%0, %1}, %2;" : "=r"(lo), "=r"(hi) : "l"(v));
    return make_float2(__uint_as_float(lo), __uint_as_float(hi));
}
__device__ __forceinline__ void cpasync16(uint32_t s, const void* g) {
    asm volatile("cp.async.cg.shared.global [%0], [%1], 16;" :: "r"(s), "l"(g));
}

// ---------------- codebook transpose [NQ][K][D] -> [NQ][D][K] ----------------
__global__ void transpose_k(const float* __restrict__ src, float* __restrict__ dst,
                            int R, int C, long srcBatch, long dstBatch) {
    __shared__ float tile[32][33];
    const float* s = src + (long)blockIdx.z * srcBatch;
    float*       d = dst + (long)blockIdx.z * dstBatch;
    int c0 = blockIdx.x * 32, r0 = blockIdx.y * 32;
    int tx = threadIdx.x, ty = threadIdx.y;           // 32 x 8
    #pragma unroll
    for (int i = 0; i < 32; i += 8)
        tile[ty + i][tx] = s[(long)(r0 + ty + i) * C + c0 + tx];
    __syncthreads();
    #pragma unroll
    for (int i = 0; i < 32; i += 8)
        d[(long)(c0 + ty + i) * R + r0 + tx] = tile[tx][ty + i];
}

// ---------------- ||c||^2 per code ----------------
__global__ void c2_k(const float* __restrict__ cb) {
    int w = (blockIdx.x * blockDim.x + threadIdx.x) >> 5;
    int lane = threadIdx.x & 31;
    if (w >= NQ * KK) return;
    const float* row = cb + (long)w * DD;
    float s = 0.f;
    #pragma unroll
    for (int j = lane; j < DD; j += 32) { float v = row[j]; s = fmaf(v, v, s); }
    #pragma unroll
    for (int o = 16; o; o >>= 1) s += __shfl_xor_sync(0xffffffffu, s, o);
    if (lane == 0) g_c2[w] = s;
}

// ---------------- fused all-stages kernel (converged configuration) ----------------
// Residual tile [256 d][64 rows] lives in smem for the whole kernel.
// 8 warps; warp w owns rows w*8..w*8+7, all 256 codes of each chunk.
// Lane l owns codes {cc*256 + l*4 + q} and {cc*256 + 128 + l*4 + q}, q=0..3.
__global__ void __launch_bounds__(NTHREADS, 2)
rvq_fused_k(const float* __restrict__ x, const float* __restrict__ cb,
            float* __restrict__ outQ, int writeQ,
            float* __restrict__ outCodes, int writeCodes) {
    extern __shared__ float sm[];
    float* Rs = sm;                           // [256][64]  64KB resident residual
    float* Bs = Rs + DD * BM;                 // [2][16][256]  2x16KB B chunks
    int*   codes_all = (int*)(Bs + 2 * BK * BNC);   // [4][64]

    const int t = threadIdx.x, lane = t & 31, w = t >> 5;
    const long rowBase = (long)blockIdx.x * BM;

    const uint32_t BsA = (uint32_t)__cvta_generic_to_shared(Bs);

    // stage B chunk for linear iteration JN into buffer JN&1
    #define STAGE_B(JN) do {                                                       \
        const int _s = (JN) >> 6, _cc = ((JN) >> 4) & 3, _dk = (JN) & 15;          \
        const uint32_t _bb = BsA + (uint32_t)((JN) & 1) * (BK * BNC * 4);          \
        const float* _src = g_cbT + ((size_t)_s * DD + _dk * BK) * KK + _cc * BNC; \
        _Pragma("unroll")                                                          \
        for (int k = 0; k < 4; k++) {                                              \
            int i4 = t + k * NTHREADS;            /* [0,1024): 16dd x 64 u16B */   \
            int dd = i4 >> 6, c4 = i4 & 63;                                        \
            cpasync16(_bb + (uint32_t)(dd * BNC + c4 * 4) * 4,                     \
                      &_src[(size_t)dd * KK + c4 * 4]);                            \
        }                                                                          \
        asm volatile("cp.async.commit_group;" ::: "memory");                       \
    } while (0)

    STAGE_B(0);

    // residual tile: direct from row-major x with in-kernel transpose.
    // thread: row = t&63, d-group = t>>6 (64 dims). LDG.128 sectored per thread;
    // STS conflict-free (lanes -> distinct rows -> distinct banks).
    {
        const int r = t & 63, dg = t >> 6;
        const float* xrow = x + (rowBase + r) * DD + dg * 64;
        #pragma unroll
        for (int i = 0; i < 16; i++) {
            float4 v = *(const float4*)&xrow[i * 4];
            Rs[(dg * 64 + i * 4 + 0) * BM + r] = v.x;
            Rs[(dg * 64 + i * 4 + 1) * BM + r] = v.y;
            Rs[(dg * 64 + i * 4 + 2) * BM + r] = v.z;
            Rs[(dg * 64 + i * 4 + 3) * BM + r] = v.w;
        }
    }

    float bestd[8];
    int   bestc[8];
    #pragma unroll
    for (int r = 0; r < 8; r++) { bestd[r] = 3.4e38f; bestc[r] = 0; }

    unsigned long long acc[8][4];   // [row][code-pair]: cp0/1 = lane*4+{01,23}, cp2/3 = +128

    for (int J = 0; J < NITER_T; J++) {
        asm volatile("cp.async.wait_group 0;" ::: "memory");
        __syncthreads();
        // safe prefetch point: all warps completed compute(J-1), the last reader
        // of buffer (J+1)&1.
        if (J + 1 < NITER_T) STAGE_B(J + 1);

        const int s = J >> 6, cc = (J >> 4) & 3, dk = J & 15;
        const float* bbuf = Bs + (J & 1) * (BK * BNC);

        if (dk == 0) {
            #pragma unroll
            for (int r = 0; r < 8; r++)
                #pragma unroll
                for (int cp = 0; cp < 4; cp++) acc[r][cp] = 0ull;
        }

        #pragma unroll
        for (int dd = 0; dd < BK; dd++) {
            const float4 a0 = *(const float4*)&Rs[(dk * BK + dd) * BM + w * 8];       // broadcast
            const float4 a1 = *(const float4*)&Rs[(dk * BK + dd) * BM + w * 8 + 4];   // broadcast
            const ulonglong2 b0 = *(const ulonglong2*)&bbuf[dd * BNC + lane * 4];        // dense
            const ulonglong2 b1 = *(const ulonglong2*)&bbuf[dd * BNC + 128 + lane * 4];  // dense
            unsigned long long A[8];
            A[0] = pack2(a0.x); A[1] = pack2(a0.y); A[2] = pack2(a0.z); A[3] = pack2(a0.w);
            A[4] = pack2(a1.x); A[5] = pack2(a1.y); A[6] = pack2(a1.z); A[7] = pack2(a1.w);
            #pragma unroll
            for (int r = 0; r < 8; r++) {
                ffma2(acc[r][0], A[r], b0.x);
                ffma2(acc[r][1], A[r], b0.y);
                ffma2(acc[r][2], A[r], b1.x);
                ffma2(acc[r][3], A[r], b1.y);
            }
        }

        if (dk == 15) {
            // dist = c2 - 2*dot ; codes ascend within each thread -> lexicographic argmin
            const float* c2p = g_c2 + s * KK;
            const float4 c2a = *(const float4*)&c2p[cc * BNC + lane * 4];
            const float4 c2b = *(const float4*)&c2p[cc * BNC + 128 + lane * 4];
            #pragma unroll
            for (int r = 0; r < 8; r++) {
                #pragma unroll
                for (int cp = 0; cp < 4; cp++) {
                    float2 dv = unpack2(acc[r][cp]);
                    int cg0 = cc * BNC + ((cp & 2) ? 128 : 0) + lane * 4 + 2 * (cp & 1);
                    float cva = (cp == 0) ? c2a.x : (cp == 1) ? c2a.z : (cp == 2) ? c2b.x : c2b.z;
                    float cvb = (cp == 0) ? c2a.y : (cp == 1) ? c2a.w : (cp == 2) ? c2b.y : c2b.w;
                    float d0 = fmaf(-2.f, dv.x, cva);
                    float d1 = fmaf(-2.f, dv.y, cvb);
                    if (d0 < bestd[r] || (d0 == bestd[r] && cg0 < bestc[r])) { bestd[r] = d0; bestc[r] = cg0; }
                    if (d1 < bestd[r] || (d1 == bestd[r] && cg0 + 1 < bestc[r])) { bestd[r] = d1; bestc[r] = cg0 + 1; }
                }
            }
        }

        // stage-end: argmin merge + in-smem residual update
        if ((J & 63) == 63) {
            #pragma unroll
            for (int r = 0; r < 8; r++) {
                float d = bestd[r]; int c = bestc[r];
                #pragma unroll
                for (int o = 16; o; o >>= 1) {
                    float od = __shfl_xor_sync(0xffffffffu, d, o);
                    int   oc = __shfl_xor_sync(0xffffffffu, c, o);
                    if (od < d || (od == d && oc < c)) { d = od; c = oc; }
                }
                if (lane == 0) codes_all[s * BM + w * 8 + r] = c;
                bestd[r] = 3.4e38f; bestc[r] = 0;
            }
            __syncthreads();            // codes_all visible to all
            if (s < NQ - 1) {
                // Rs[d][r] -= cb_s[code_r][d]; thread: r = t&63, d-group = t>>6.
                // float4 gather (16 LDG.128) + conflict-free scalar smem RMW.
                const int r = t & 63, dg = t >> 6;
                const int code = codes_all[s * BM + r];
                const float* crow = cb + ((size_t)s * KK + code) * DD + dg * 64;
                #pragma unroll
                for (int i = 0; i < 16; i++) {
                    float4 v = *(const float4*)&crow[i * 4];
                    Rs[(dg * 64 + i * 4 + 0) * BM + r] -= v.x;
                    Rs[(dg * 64 + i * 4 + 1) * BM + r] -= v.y;
                    Rs[(dg * 64 + i * 4 + 2) * BM + r] -= v.z;
                    Rs[(dg * 64 + i * 4 + 3) * BM + r] -= v.w;
                }
            }
            // the next loop-head __syncthreads orders this update before stage s+1 compute
        }
    }
    #undef STAGE_B

    // codes output: one coalesced STG.128 per row (all 4 stages packed)
    if (writeCodes && t < BM) {
        float4 cv;
        cv.x = (float)codes_all[t];
        cv.y = (float)codes_all[BM + t];
        cv.z = (float)codes_all[2 * BM + t];
        cv.w = (float)codes_all[3 * BM + t];
        *(float4*)&outCodes[(rowBase + t) * NQ] = cv;
    }

    // quantised output: out[row] = ((cb0[c0] + cb1[c1]) + cb2[c2]) + cb3[c3]
    // (matches the reference scan's sequential total accumulation order)
    if (writeQ) {
        #pragma unroll
        for (int rr = 0; rr < 8; rr++) {
            int row = w * 8 + rr;
            int c0 = codes_all[row];
            int c1 = codes_all[BM + row];
            int c2 = codes_all[2 * BM + row];
            int c3 = codes_all[3 * BM + row];
            const float4* q0 = (const float4*)(cb + (size_t)c0 * DD);
            const float4* q1 = (const float4*)(cb + ((size_t)KK + c1) * DD);
            const float4* q2 = (const float4*)(cb + ((size_t)2 * KK + c2) * DD);
            const float4* q3 = (const float4*)(cb + ((size_t)3 * KK + c3) * DD);
            float4* orow = (float4*)(outQ + (rowBase + row) * DD);
            #pragma unroll
            for (int dq = 0; dq < 2; dq++) {
                int idx = lane + dq * 32;
                float4 v0 = q0[idx], v1 = q1[idx], v2 = q2[idx], v3 = q3[idx];
                float4 o;
                o.x = ((v0.x + v1.x) + v2.x) + v3.x;
                o.y = ((v0.y + v1.y) + v2.y) + v3.y;
                o.z = ((v0.z + v1.z) + v2.z) + v3.z;
                o.w = ((v0.w + v1.w) + v2.w) + v3.w;
                orow[idx] = o;
            }
        }
    }
}

// ---------------- launch ----------------
extern "C" void kernel_launch(void* const* d_in, const int* in_sizes, int n_in,
                              void* d_out, int out_size) {
    const float* x  = (const float*)d_in[0];
    const float* cb = (const float*)d_in[1];
    float* out = (float*)d_out;

    const long QE = (long)NTOT * DD;
    const long CE = (long)NTOT * NQ;

    int writeQ = (out_size >= QE) ? 1 : 0;
    float* outCodes = nullptr;
    int writeCodes = 0;
    if ((long)out_size >= QE + CE) { outCodes = out + QE; writeCodes = 1; }
    else if (!writeQ && (long)out_size >= CE) { outCodes = out; writeCodes = 1; }

    const int SMEM = (DD * BM + 2 * BK * BNC) * 4 + NQ * BM * 4;   // 99328 B
    cudaFuncSetAttribute(rvq_fused_k, cudaFuncAttributeMaxDynamicSharedMemorySize, SMEM);

    float* cbT_ptr = nullptr;
    cudaGetSymbolAddress((void**)&cbT_ptr, g_cbT);

    dim3 tb(32, 8);
    // codebooks [NQ][K][D] -> [NQ][D][K]
    transpose_k<<<dim3(DD / 32, KK / 32, NQ), tb>>>(cb, cbT_ptr, KK, DD,
                                                    (long)KK * DD, (long)DD * KK);
    c2_k<<<(NQ * KK * 32 + 255) / 256, 256>>>(cb);

    rvq_fused_k<<<NTOT / BM, NTHREADS, SMEM>>>(x, cb, out, writeQ, outCodes, writeCodes);
}

// round 17
// speedup vs baseline: 1.0648x; 1.0001x over previous
#include <cuda_runtime.h>
#include <cstdint>

// Problem constants
#define DD   256
#define NQ   4
#define KK   1024
#define NTOT 131072

// Tiling
#define BM   64               // rows per CTA (8 warps x 8 rows), resident in smem
#define BNC  256              // codes per chunk
#define BK   16               // d per staged B chunk
#define NTHREADS 256
#define NITER_T  256          // 4 stages * 4 cc * 16 dk

// Scratch (read-only after prep)
__device__ float g_cbT[(size_t)NQ * DD * KK];   // codebooks transposed [s][d][k]
__device__ float g_c2[NQ * KK];                 // ||c||^2 per code

// ---------------- packed f32x2 helpers ----------------
__device__ __forceinline__ unsigned long long pack2(float x) {
    unsigned long long r;
    unsigned int xi = __float_as_uint(x);
    asm("mov.b64 %0, {%1, %1};" : "=l"(r) : "r"(xi));
    return r;
}
__device__ __forceinline__ void ffma2(unsigned long long &acc,
                                      unsigned long long a,
                                      unsigned long long b) {
    asm("fma.rn.f32x2 %0, %1, %2, %0;" : "+l"(acc) : "l"(a), "l"(b));
}
__device__ __forceinline__ float2 unpack2(unsigned long long v) {
    unsigned int lo, hi;
    asm("mov.b64 {%0, %1}, %2;" : "=r"(lo), "=r"(hi) : "l"(v));
    return make_float2(__uint_as_float(lo), __uint_as_float(hi));
}
__device__ __forceinline__ void cpasync16(uint32_t s, const void* g) {
    asm volatile("cp.async.cg.shared.global [%0], [%1], 16;" :: "r"(s), "l"(g));
}

// ---------------- fused prep: codebook transpose + ||c||^2 ----------------
// Blocks [0,1024): transpose cb [NQ][K][D] -> g_cbT [NQ][D][K] (32x32 tiles).
// Blocks [1024,1536): per-code squared norms (one warp per code).
// Both halves only read cb; they run concurrently in one launch.
__global__ void prep_k(const float* __restrict__ cb) {
    const int b = blockIdx.x;
    if (b < 1024) {
        __shared__ float tile[32][33];
        // decompose: bx in [0,8) over D, by in [0,32) over K, bz in [0,4) stage
        const int bx = b & 7, by = (b >> 3) & 31, bz = b >> 8;
        const float* s = cb + (size_t)bz * KK * DD;
        float*       d = g_cbT + (size_t)bz * DD * KK;
        const int c0 = bx * 32, r0 = by * 32;       // c over D, r over K
        const int tx = threadIdx.x & 31, ty = threadIdx.x >> 5;   // 32 x 8
        #pragma unroll
        for (int i = 0; i < 32; i += 8)
            tile[ty + i][tx] = s[(size_t)(r0 + ty + i) * DD + c0 + tx];
        __syncthreads();
        #pragma unroll
        for (int i = 0; i < 32; i += 8)
            d[(size_t)(c0 + ty + i) * KK + r0 + tx] = tile[tx][ty + i];
    } else {
        const int cb_blk = b - 1024;                // [0,512)
        const int wz = (cb_blk * NTHREADS + threadIdx.x) >> 5;  // global code id
        const int lane = threadIdx.x & 31;
        if (wz >= NQ * KK) return;
        const float* row = cb + (size_t)wz * DD;
        float s = 0.f;
        #pragma unroll
        for (int j = lane; j < DD; j += 32) { float v = row[j]; s = fmaf(v, v, s); }
        #pragma unroll
        for (int o = 16; o; o >>= 1) s += __shfl_xor_sync(0xffffffffu, s, o);
        if (lane == 0) g_c2[wz] = s;
    }
}

// ---------------- fused all-stages kernel (converged configuration) ----------------
// Residual tile [256 d][64 rows] lives in smem for the whole kernel.
// 8 warps; warp w owns rows w*8..w*8+7, all 256 codes of each chunk.
// Lane l owns codes {cc*256 + l*4 + q} and {cc*256 + 128 + l*4 + q}, q=0..3.
__global__ void __launch_bounds__(NTHREADS, 2)
rvq_fused_k(const float* __restrict__ x, const float* __restrict__ cb,
            float* __restrict__ outQ, int writeQ,
            float* __restrict__ outCodes, int writeCodes) {
    extern __shared__ float sm[];
    float* Rs = sm;                           // [256][64]  64KB resident residual
    float* Bs = Rs + DD * BM;                 // [2][16][256]  2x16KB B chunks
    int*   codes_all = (int*)(Bs + 2 * BK * BNC);   // [4][64]

    const int t = threadIdx.x, lane = t & 31, w = t >> 5;
    const long rowBase = (long)blockIdx.x * BM;

    const uint32_t BsA = (uint32_t)__cvta_generic_to_shared(Bs);

    // stage B chunk for linear iteration JN into buffer JN&1
    #define STAGE_B(JN) do {                                                       \
        const int _s = (JN) >> 6, _cc = ((JN) >> 4) & 3, _dk = (JN) & 15;          \
        const uint32_t _bb = BsA + (uint32_t)((JN) & 1) * (BK * BNC * 4);          \
        const float* _src = g_cbT + ((size_t)_s * DD + _dk * BK) * KK + _cc * BNC; \
        _Pragma("unroll")                                                          \
        for (int k = 0; k < 4; k++) {                                              \
            int i4 = t + k * NTHREADS;            /* [0,1024): 16dd x 64 u16B */   \
            int dd = i4 >> 6, c4 = i4 & 63;                                        \
            cpasync16(_bb + (uint32_t)(dd * BNC + c4 * 4) * 4,                     \
                      &_src[(size_t)dd * KK + c4 * 4]);                            \
        }                                                                          \
        asm volatile("cp.async.commit_group;" ::: "memory");                       \
    } while (0)

    STAGE_B(0);

    // residual tile: direct from row-major x with in-kernel transpose.
    // thread: row = t&63, d-group = t>>6 (64 dims). LDG.128 sectored per thread;
    // STS conflict-free (lanes -> distinct rows -> distinct banks).
    {
        const int r = t & 63, dg = t >> 6;
        const float* xrow = x + (rowBase + r) * DD + dg * 64;
        #pragma unroll
        for (int i = 0; i < 16; i++) {
            float4 v = *(const float4*)&xrow[i * 4];
            Rs[(dg * 64 + i * 4 + 0) * BM + r] = v.x;
            Rs[(dg * 64 + i * 4 + 1) * BM + r] = v.y;
            Rs[(dg * 64 + i * 4 + 2) * BM + r] = v.z;
            Rs[(dg * 64 + i * 4 + 3) * BM + r] = v.w;
        }
    }

    float bestd[8];
    int   bestc[8];
    #pragma unroll
    for (int r = 0; r < 8; r++) { bestd[r] = 3.4e38f; bestc[r] = 0; }

    unsigned long long acc[8][4];   // [row][code-pair]: cp0/1 = lane*4+{01,23}, cp2/3 = +128

    for (int J = 0; J < NITER_T; J++) {
        asm volatile("cp.async.wait_group 0;" ::: "memory");
        __syncthreads();
        // safe prefetch point: all warps completed compute(J-1), the last reader
        // of buffer (J+1)&1.
        if (J + 1 < NITER_T) STAGE_B(J + 1);

        const int s = J >> 6, cc = (J >> 4) & 3, dk = J & 15;
        const float* bbuf = Bs + (J & 1) * (BK * BNC);

        if (dk == 0) {
            #pragma unroll
            for (int r = 0; r < 8; r++)
                #pragma unroll
                for (int cp = 0; cp < 4; cp++) acc[r][cp] = 0ull;
        }

        #pragma unroll
        for (int dd = 0; dd < BK; dd++) {
            const float4 a0 = *(const float4*)&Rs[(dk * BK + dd) * BM + w * 8];       // broadcast
            const float4 a1 = *(const float4*)&Rs[(dk * BK + dd) * BM + w * 8 + 4];   // broadcast
            const ulonglong2 b0 = *(const ulonglong2*)&bbuf[dd * BNC + lane * 4];        // dense
            const ulonglong2 b1 = *(const ulonglong2*)&bbuf[dd * BNC + 128 + lane * 4];  // dense
            unsigned long long A[8];
            A[0] = pack2(a0.x); A[1] = pack2(a0.y); A[2] = pack2(a0.z); A[3] = pack2(a0.w);
            A[4] = pack2(a1.x); A[5] = pack2(a1.y); A[6] = pack2(a1.z); A[7] = pack2(a1.w);
            #pragma unroll
            for (int r = 0; r < 8; r++) {
                ffma2(acc[r][0], A[r], b0.x);
                ffma2(acc[r][1], A[r], b0.y);
                ffma2(acc[r][2], A[r], b1.x);
                ffma2(acc[r][3], A[r], b1.y);
            }
        }

        if (dk == 15) {
            // dist = c2 - 2*dot ; codes ascend within each thread -> lexicographic argmin
            const float* c2p = g_c2 + s * KK;
            const float4 c2a = *(const float4*)&c2p[cc * BNC + lane * 4];
            const float4 c2b = *(const float4*)&c2p[cc * BNC + 128 + lane * 4];
            #pragma unroll
            for (int r = 0; r < 8; r++) {
                #pragma unroll
                for (int cp = 0; cp < 4; cp++) {
                    float2 dv = unpack2(acc[r][cp]);
                    int cg0 = cc * BNC + ((cp & 2) ? 128 : 0) + lane * 4 + 2 * (cp & 1);
                    float cva = (cp == 0) ? c2a.x : (cp == 1) ? c2a.z : (cp == 2) ? c2b.x : c2b.z;
                    float cvb = (cp == 0) ? c2a.y : (cp == 1) ? c2a.w : (cp == 2) ? c2b.y : c2b.w;
                    float d0 = fmaf(-2.f, dv.x, cva);
                    float d1 = fmaf(-2.f, dv.y, cvb);
                    if (d0 < bestd[r] || (d0 == bestd[r] && cg0 < bestc[r])) { bestd[r] = d0; bestc[r] = cg0; }
                    if (d1 < bestd[r] || (d1 == bestd[r] && cg0 + 1 < bestc[r])) { bestd[r] = d1; bestc[r] = cg0 + 1; }
                }
            }
        }

        // stage-end: argmin merge + in-smem residual update
        if ((J & 63) == 63) {
            #pragma unroll
            for (int r = 0; r < 8; r++) {
                float d = bestd[r]; int c = bestc[r];
                #pragma unroll
                for (int o = 16; o; o >>= 1) {
                    float od = __shfl_xor_sync(0xffffffffu, d, o);
                    int   oc = __shfl_xor_sync(0xffffffffu, c, o);
                    if (od < d || (od == d && oc < c)) { d = od; c = oc; }
                }
                if (lane == 0) codes_all[s * BM + w * 8 + r] = c;
                bestd[r] = 3.4e38f; bestc[r] = 0;
            }
            __syncthreads();            // codes_all visible to all
            if (s < NQ - 1) {
                // Rs[d][r] -= cb_s[code_r][d]; thread: r = t&63, d-group = t>>6.
                // float4 gather (16 LDG.128) + conflict-free scalar smem RMW.
                const int r = t & 63, dg = t >> 6;
                const int code = codes_all[s * BM + r];
                const float* crow = cb + ((size_t)s * KK + code) * DD + dg * 64;
                #pragma unroll
                for (int i = 0; i < 16; i++) {
                    float4 v = *(const float4*)&crow[i * 4];
                    Rs[(dg * 64 + i * 4 + 0) * BM + r] -= v.x;
                    Rs[(dg * 64 + i * 4 + 1) * BM + r] -= v.y;
                    Rs[(dg * 64 + i * 4 + 2) * BM + r] -= v.z;
                    Rs[(dg * 64 + i * 4 + 3) * BM + r] -= v.w;
                }
            }
            // the next loop-head __syncthreads orders this update before stage s+1 compute
        }
    }
    #undef STAGE_B

    // codes output: one coalesced STG.128 per row (all 4 stages packed)
    if (writeCodes && t < BM) {
        float4 cv;
        cv.x = (float)codes_all[t];
        cv.y = (float)codes_all[BM + t];
        cv.z = (float)codes_all[2 * BM + t];
        cv.w = (float)codes_all[3 * BM + t];
        *(float4*)&outCodes[(rowBase + t) * NQ] = cv;
    }

    // quantised output: out[row] = ((cb0[c0] + cb1[c1]) + cb2[c2]) + cb3[c3]
    // (matches the reference scan's sequential total accumulation order)
    if (writeQ) {
        #pragma unroll
        for (int rr = 0; rr < 8; rr++) {
            int row = w * 8 + rr;
            int c0 = codes_all[row];
            int c1 = codes_all[BM + row];
            int c2 = codes_all[2 * BM + row];
            int c3 = codes_all[3 * BM + row];
            const float4* q0 = (const float4*)(cb + (size_t)c0 * DD);
            const float4* q1 = (const float4*)(cb + ((size_t)KK + c1) * DD);
            const float4* q2 = (const float4*)(cb + ((size_t)2 * KK + c2) * DD);
            const float4* q3 = (const float4*)(cb + ((size_t)3 * KK + c3) * DD);
            float4* orow = (float4*)(outQ + (rowBase + row) * DD);
            #pragma unroll
            for (int dq = 0; dq < 2; dq++) {
                int idx = lane + dq * 32;
                float4 v0 = q0[idx], v1 = q1[idx], v2 = q2[idx], v3 = q3[idx];
                float4 o;
                o.x = ((v0.x + v1.x) + v2.x) + v3.x;
                o.y = ((v0.y + v1.y) + v2.y) + v3.y;
                o.z = ((v0.z + v1.z) + v2.z) + v3.z;
                o.w = ((v0.w + v1.w) + v2.w) + v3.w;
                orow[idx] = o;
            }
        }
    }
}

// ---------------- launch ----------------
extern "C" void kernel_launch(void* const* d_in, const int* in_sizes, int n_in,
                              void* d_out, int out_size) {
    const float* x  = (const float*)d_in[0];
    const float* cb = (const float*)d_in[1];
    float* out = (float*)d_out;

    const long QE = (long)NTOT * DD;
    const long CE = (long)NTOT * NQ;

    int writeQ = (out_size >= QE) ? 1 : 0;
    float* outCodes = nullptr;
    int writeCodes = 0;
    if ((long)out_size >= QE + CE) { outCodes = out + QE; writeCodes = 1; }
    else if (!writeQ && (long)out_size >= CE) { outCodes = out; writeCodes = 1; }

    const int SMEM = (DD * BM + 2 * BK * BNC) * 4 + NQ * BM * 4;   // 99328 B
    cudaFuncSetAttribute(rvq_fused_k, cudaFuncAttributeMaxDynamicSharedMemorySize, SMEM);

    // fused prep: codebook transpose (blocks 0-1023) + c2 (blocks 1024-1535)
    prep_k<<<1536, NTHREADS>>>(cb);

    rvq_fused_k<<<NTOT / BM, NTHREADS, SMEM>>>(x, cb, out, writeQ, outCodes, writeCodes);
}